// round 5
// baseline (speedup 1.0000x reference)
#include <cuda_runtime.h>
#include <cstdint>
#include <cstddef>

// Problem constants
#define DIAGNUM 50000
#define MEDNUM  20000
#define PRONUM  40000
#define FEATDIM 128
#define N1 (DIAGNUM + MEDNUM)   // 70000
#define N2 (PRONUM + MEDNUM)    // 60000
#define NNZ1 1120000
#define NNZ2 960000
#define CAP 64                  // Poisson(16): P(deg>64) ~ 1e-21 (clamped anyway)

#define NCNT (2 * N1 + 2 * N2)  // 260000 counters

// NOTE: buckets are only ever written with valid cols for their graph, and the
// initial zero-fill is also a valid col (0). So over-reading up to CAP slots is
// always safe; stale entries are neutralized by zeroing their value via select.
__device__ int  g_cnt[NCNT];
__device__ int2 g_bkt1[(size_t)2 * N1 * CAP];      // graph1: lists 0,1
__device__ int2 g_bkt2[(size_t)2 * N2 * CAP];      // graph2: lists 0,1
__device__ float g_mg1[(size_t)MEDNUM * FEATDIM];  // m-row g1 partial
__device__ float g_mg2[(size_t)MEDNUM * FEATDIM];  // m-row g2 partial

// ---------------------------------------------------------------------------
__global__ void zero_cnt_kernel() {
    int i = blockIdx.x * blockDim.x + threadIdx.x;
    if (i < NCNT) g_cnt[i] = 0;
}

// ---------------------------------------------------------------------------
// Bucket scatter: one thread per edge, all four adjacency lists in one launch.
// ---------------------------------------------------------------------------
__global__ void bucket_kernel(const int* __restrict__ r1, const int* __restrict__ c1,
                              const float* __restrict__ v1,
                              const int* __restrict__ r2, const int* __restrict__ c2,
                              const float* __restrict__ v2,
                              int2* __restrict__ bkt1, int2* __restrict__ bkt2) {
    int idx = blockIdx.x * blockDim.x + threadIdx.x;
    if (idx < 2 * NNZ1) {
        int list = (idx >= NNZ1) ? 1 : 0;
        int r = __ldg(r1 + idx);
        int c = __ldg(c1 + idx);
        float v = __ldg(v1 + idx);
        int base = list * N1 + r;
        int slot = atomicAdd(&g_cnt[base], 1);
        if (slot < CAP)
            bkt1[(size_t)base * CAP + slot] = make_int2(c, __float_as_int(v));
    } else {
        int j = idx - 2 * NNZ1;
        if (j >= 2 * NNZ2) return;
        int list = (j >= NNZ2) ? 1 : 0;
        int r = __ldg(r2 + j);
        int c = __ldg(c2 + j);
        float v = __ldg(v2 + j);
        int base = list * N2 + r;
        int slot = atomicAdd(&g_cnt[2 * N1 + base], 1);
        if (slot < CAP)
            bkt2[(size_t)base * CAP + slot] = make_int2(c, __float_as_int(v));
    }
}

// ---------------------------------------------------------------------------
// Pair accumulation, software-pipelined & branch-free:
//   per iteration: 4x int4 edge-pack loads (8 edges) -> 8 gather LDG.128 ->
//   value-select (0 beyond count) -> 32 FFMA. One basic block => ptxas
//   front-batches all loads => ~8 outstanding gathers per warp.
// ---------------------------------------------------------------------------
__device__ __forceinline__ void pair_accum(const int2* __restrict__ b0, int n0,
                                           const int2* __restrict__ b1, int n1,
                                           const float4* __restrict__ srcA, int nA,
                                           const float4* __restrict__ srcB,
                                           int lane, float4& ha, float4& hb) {
    ha = make_float4(0.f, 0.f, 0.f, 0.f);
    hb = make_float4(0.f, 0.f, 0.f, 0.f);
    int nmax = max(n0, n1);
    #pragma unroll 1
    for (int s = 0; s < nmax; s += 4) {
        // 8 edges (4 per list) via int4 packs — always in-bounds (CAP=64)
        int4 p0 = __ldg(reinterpret_cast<const int4*>(b0 + s));
        int4 p1 = __ldg(reinterpret_cast<const int4*>(b0 + s + 2));
        int4 q0 = __ldg(reinterpret_cast<const int4*>(b1 + s));
        int4 q1 = __ldg(reinterpret_cast<const int4*>(b1 + s + 2));

        int   ca[4] = {p0.x, p0.z, p1.x, p1.z};
        float va[4] = {__int_as_float(p0.y), __int_as_float(p0.w),
                       __int_as_float(p1.y), __int_as_float(p1.w)};
        int   cb[4] = {q0.x, q0.z, q1.x, q1.z};
        float vb[4] = {__int_as_float(q0.y), __int_as_float(q0.w),
                       __int_as_float(q1.y), __int_as_float(q1.w)};

        float4 xa[4], xb[4];
        #pragma unroll
        for (int j = 0; j < 4; j++) {
            const float4* sa = ((ca[j] < nA) ? srcA + (size_t)ca[j] * 32
                                             : srcB + (size_t)(ca[j] - nA) * 32) + lane;
            const float4* sb = ((cb[j] < nA) ? srcA + (size_t)cb[j] * 32
                                             : srcB + (size_t)(cb[j] - nA) * 32) + lane;
            xa[j] = __ldg(sa);
            xb[j] = __ldg(sb);
        }

        #pragma unroll
        for (int j = 0; j < 4; j++) {
            float wa = (s + j < n0) ? va[j] : 0.f;
            float wb = (s + j < n1) ? vb[j] : 0.f;
            ha.x = fmaf(wa, xa[j].x, ha.x);
            ha.y = fmaf(wa, xa[j].y, ha.y);
            ha.z = fmaf(wa, xa[j].z, ha.z);
            ha.w = fmaf(wa, xa[j].w, ha.w);
            hb.x = fmaf(wb, xb[j].x, hb.x);
            hb.y = fmaf(wb, xb[j].y, hb.y);
            hb.z = fmaf(wb, xb[j].z, hb.z);
            hb.w = fmaf(wb, xb[j].w, hb.w);
        }
    }
}

__device__ __forceinline__ float4 relu_add4(float4 a, float4 b) {
    return make_float4(fmaxf(a.x, 0.f) + fmaxf(b.x, 0.f),
                       fmaxf(a.y, 0.f) + fmaxf(b.y, 0.f),
                       fmaxf(a.z, 0.f) + fmaxf(b.z, 0.f),
                       fmaxf(a.w, 0.f) + fmaxf(b.w, 0.f));
}

// ---------------------------------------------------------------------------
// Gather: one warp per TASK (one list-pair) — perfectly balanced.
// ---------------------------------------------------------------------------
#define NTASKS 130000

__global__ void gather_kernel(const float4* __restrict__ dE,
                              const float4* __restrict__ mE,
                              const float4* __restrict__ pE,
                              float4* __restrict__ out) {
    int task = (blockIdx.x * blockDim.x + threadIdx.x) >> 5;
    int lane = threadIdx.x & 31;
    if (task >= NTASKS) return;

    float4 ha, hb;
    if (task < 50000) {                       // d-row, graph1
        int r = task;
        int n0 = min(g_cnt[r], CAP);
        int n1 = min(g_cnt[N1 + r], CAP);
        pair_accum(g_bkt1 + (size_t)r * CAP, n0,
                   g_bkt1 + (size_t)(N1 + r) * CAP, n1,
                   dE, DIAGNUM, mE, lane, ha, hb);
        float4 g = relu_add4(ha, hb);
        out[(size_t)(MEDNUM + r) * 32 + lane] =
            make_float4(2.f * g.x, 2.f * g.y, 2.f * g.z, 2.f * g.w);
    } else if (task < 90000) {                // p-row, graph2
        int r = task - 50000;
        int n0 = min(g_cnt[2 * N1 + r], CAP);
        int n1 = min(g_cnt[2 * N1 + N2 + r], CAP);
        pair_accum(g_bkt2 + (size_t)r * CAP, n0,
                   g_bkt2 + (size_t)(N2 + r) * CAP, n1,
                   pE, PRONUM, mE, lane, ha, hb);
        float4 g = relu_add4(ha, hb);
        out[(size_t)(MEDNUM + DIAGNUM + r) * 32 + lane] =
            make_float4(2.f * g.x, 2.f * g.y, 2.f * g.z, 2.f * g.w);
    } else if (task < 110000) {               // m-row, graph1 partial
        int m = task - 90000;
        int r = DIAGNUM + m;
        int n0 = min(g_cnt[r], CAP);
        int n1 = min(g_cnt[N1 + r], CAP);
        pair_accum(g_bkt1 + (size_t)r * CAP, n0,
                   g_bkt1 + (size_t)(N1 + r) * CAP, n1,
                   dE, DIAGNUM, mE, lane, ha, hb);
        reinterpret_cast<float4*>(g_mg1)[(size_t)m * 32 + lane] = relu_add4(ha, hb);
    } else {                                  // m-row, graph2 partial
        int m = task - 110000;
        int r = PRONUM + m;
        int n0 = min(g_cnt[2 * N1 + r], CAP);
        int n1 = min(g_cnt[2 * N1 + N2 + r], CAP);
        pair_accum(g_bkt2 + (size_t)r * CAP, n0,
                   g_bkt2 + (size_t)(N2 + r) * CAP, n1,
                   pE, PRONUM, mE, lane, ha, hb);
        reinterpret_cast<float4*>(g_mg2)[(size_t)m * 32 + lane] = relu_add4(ha, hb);
    }
}

// ---------------------------------------------------------------------------
// Blend the m-row partials: out[0..20000) = 2*(t*g1 + (1-t)*g2)
// ---------------------------------------------------------------------------
__global__ void m_combine_kernel(const float* __restrict__ inter,
                                 float4* __restrict__ out) {
    int i = blockIdx.x * blockDim.x + threadIdx.x;
    if (i >= MEDNUM * 32) return;
    float t = __ldg(inter);
    float u = 1.f - t;
    float4 a = reinterpret_cast<const float4*>(g_mg1)[i];
    float4 b = reinterpret_cast<const float4*>(g_mg2)[i];
    out[i] = make_float4(2.f * (t * a.x + u * b.x),
                         2.f * (t * a.y + u * b.y),
                         2.f * (t * a.z + u * b.z),
                         2.f * (t * a.w + u * b.w));
}

// ---------------------------------------------------------------------------
extern "C" void kernel_launch(void* const* d_in, const int* in_sizes, int n_in,
                              void* d_out, int out_size) {
    const int*   a1r = (const int*)d_in[0];
    const int*   a1c = (const int*)d_in[1];
    const float* a1v = (const float*)d_in[2];
    const int*   a2r = (const int*)d_in[3];
    const int*   a2c = (const int*)d_in[4];
    const float* a2v = (const float*)d_in[5];
    const float4* dE = (const float4*)d_in[6];
    const float4* mE = (const float4*)d_in[7];
    const float4* pE = (const float4*)d_in[8];
    const float* inter = (const float*)d_in[9];
    float4* out = (float4*)d_out;

    int2* bkt1;  cudaGetSymbolAddress((void**)&bkt1, g_bkt1);
    int2* bkt2;  cudaGetSymbolAddress((void**)&bkt2, g_bkt2);

    // 1. Zero counters
    {
        int threads = 256;
        int blocks = (NCNT + threads - 1) / threads;
        zero_cnt_kernel<<<blocks, threads>>>();
    }

    // 2. Bucket all four adjacency lists in one launch
    {
        int total = 2 * NNZ1 + 2 * NNZ2;
        int threads = 256;
        int blocks = (total + threads - 1) / threads;
        bucket_kernel<<<blocks, threads>>>(a1r, a1c, a1v, a2r, a2c, a2v, bkt1, bkt2);
    }

    // 3. Balanced fused gather (one warp per list-pair task)
    {
        int threads = 256;
        int blocks = (NTASKS * 32 + threads - 1) / threads;
        gather_kernel<<<blocks, threads>>>(dE, mE, pE, out);
    }

    // 4. Blend m-row partials
    {
        int threads = 256;
        int blocks = (MEDNUM * 32 + threads - 1) / threads;
        m_combine_kernel<<<blocks, threads>>>(inter, out);
    }
}

// round 8
// speedup vs baseline: 1.0709x; 1.0709x over previous
#include <cuda_runtime.h>
#include <cuda_fp16.h>
#include <cstdint>
#include <cstddef>

// Problem constants
#define DIAGNUM 50000
#define MEDNUM  20000
#define PRONUM  40000
#define FEATDIM 128
#define N1 (DIAGNUM + MEDNUM)   // 70000
#define N2 (PRONUM + MEDNUM)    // 60000
#define NNZ1 1120000
#define NNZ2 960000
#define CAP 64                  // Poisson(16): P(deg>64) ~ 1e-21 (clamped anyway)

#define NCNT (2 * N1 + 2 * N2)  // 260000 counters

__device__ int  g_cnt[NCNT];
__device__ int2 g_bkt1[(size_t)2 * N1 * CAP];      // graph1: lists 0,1
__device__ int2 g_bkt2[(size_t)2 * N2 * CAP];      // graph2: lists 0,1
__device__ float g_mg1[(size_t)MEDNUM * FEATDIM];  // m-row g1 partial
__device__ float g_mg2[(size_t)MEDNUM * FEATDIM];  // m-row g2 partial

// fp16 concatenated embedding tables (gathers read these: half the L2 bytes)
__device__ __half g_e1[(size_t)N1 * FEATDIM];      // [dEmbed | mEmbed] 17.9 MB
__device__ __half g_e2[(size_t)N2 * FEATDIM];      // [pEmbed | mEmbed] 15.4 MB

// ---------------------------------------------------------------------------
__global__ void zero_cnt_kernel() {
    int i = blockIdx.x * blockDim.x + threadIdx.x;
    if (i < NCNT) g_cnt[i] = 0;
}

// ---------------------------------------------------------------------------
// Convert fp32 embeddings -> fp16 concatenated tables.
// One thread per float4 (4 elems -> 2x half2 = 8B).
// ---------------------------------------------------------------------------
__global__ void convert_kernel(const float4* __restrict__ dE,
                               const float4* __restrict__ mE,
                               const float4* __restrict__ pE) {
    const int q1 = N1 * FEATDIM / 4;   // 2,240,000 float4 in e1
    const int q2 = N2 * FEATDIM / 4;   // 1,920,000 float4 in e2
    const int qd = DIAGNUM * FEATDIM / 4;
    const int qp = PRONUM * FEATDIM / 4;
    int i = blockIdx.x * blockDim.x + threadIdx.x;
    if (i < q1) {
        float4 x = (i < qd) ? __ldg(dE + i) : __ldg(mE + (i - qd));
        __half2 lo = __floats2half2_rn(x.x, x.y);
        __half2 hi = __floats2half2_rn(x.z, x.w);
        uint2 packed;
        packed.x = *reinterpret_cast<unsigned*>(&lo);
        packed.y = *reinterpret_cast<unsigned*>(&hi);
        reinterpret_cast<uint2*>(g_e1)[i] = packed;
    } else {
        int j = i - q1;
        if (j >= q2) return;
        float4 x = (j < qp) ? __ldg(pE + j) : __ldg(mE + (j - qp));
        __half2 lo = __floats2half2_rn(x.x, x.y);
        __half2 hi = __floats2half2_rn(x.z, x.w);
        uint2 packed;
        packed.x = *reinterpret_cast<unsigned*>(&lo);
        packed.y = *reinterpret_cast<unsigned*>(&hi);
        reinterpret_cast<uint2*>(g_e2)[j] = packed;
    }
}

// ---------------------------------------------------------------------------
// Bucket scatter: one thread per edge, all four adjacency lists in one launch.
// ---------------------------------------------------------------------------
__global__ void bucket_kernel(const int* __restrict__ r1, const int* __restrict__ c1,
                              const float* __restrict__ v1,
                              const int* __restrict__ r2, const int* __restrict__ c2,
                              const float* __restrict__ v2,
                              int2* __restrict__ bkt1, int2* __restrict__ bkt2) {
    int idx = blockIdx.x * blockDim.x + threadIdx.x;
    if (idx < 2 * NNZ1) {
        int list = (idx >= NNZ1) ? 1 : 0;
        int r = __ldg(r1 + idx);
        int c = __ldg(c1 + idx);
        float v = __ldg(v1 + idx);
        int base = list * N1 + r;
        int slot = atomicAdd(&g_cnt[base], 1);
        if (slot < CAP)
            bkt1[(size_t)base * CAP + slot] = make_int2(c, __float_as_int(v));
    } else {
        int j = idx - 2 * NNZ1;
        if (j >= 2 * NNZ2) return;
        int list = (j >= NNZ2) ? 1 : 0;
        int r = __ldg(r2 + j);
        int c = __ldg(c2 + j);
        float v = __ldg(v2 + j);
        int base = list * N2 + r;
        int slot = atomicAdd(&g_cnt[2 * N1 + base], 1);
        if (slot < CAP)
            bkt2[(size_t)base * CAP + slot] = make_int2(c, __float_as_int(v));
    }
}

// ---------------------------------------------------------------------------
// Pair accumulation over fp16 table: lane loads 8B (4 halfs) per gather.
// Predicated interleave of the two lists (the 272us-proven structure).
// ---------------------------------------------------------------------------
__device__ __forceinline__ void pair_accum(const int2* __restrict__ b0, int n0,
                                           const int2* __restrict__ b1, int n1,
                                           const uint2* __restrict__ tbl,
                                           int lane, float4& ha, float4& hb) {
    ha = make_float4(0.f, 0.f, 0.f, 0.f);
    hb = make_float4(0.f, 0.f, 0.f, 0.f);
    int nmax = max(n0, n1);
    #pragma unroll 4
    for (int k = 0; k < nmax; k++) {
        if (k < n0) {
            int2 e = __ldg(b0 + k);
            float v = __int_as_float(e.y);
            uint2 p = __ldg(tbl + (size_t)e.x * 32 + lane);
            float2 lo = __half22float2(*reinterpret_cast<__half2*>(&p.x));
            float2 hi = __half22float2(*reinterpret_cast<__half2*>(&p.y));
            ha.x = fmaf(v, lo.x, ha.x);
            ha.y = fmaf(v, lo.y, ha.y);
            ha.z = fmaf(v, hi.x, ha.z);
            ha.w = fmaf(v, hi.y, ha.w);
        }
        if (k < n1) {
            int2 e = __ldg(b1 + k);
            float v = __int_as_float(e.y);
            uint2 p = __ldg(tbl + (size_t)e.x * 32 + lane);
            float2 lo = __half22float2(*reinterpret_cast<__half2*>(&p.x));
            float2 hi = __half22float2(*reinterpret_cast<__half2*>(&p.y));
            hb.x = fmaf(v, lo.x, hb.x);
            hb.y = fmaf(v, lo.y, hb.y);
            hb.z = fmaf(v, hi.x, hb.z);
            hb.w = fmaf(v, hi.y, hb.w);
        }
    }
}

__device__ __forceinline__ float4 relu_add4(float4 a, float4 b) {
    return make_float4(fmaxf(a.x, 0.f) + fmaxf(b.x, 0.f),
                       fmaxf(a.y, 0.f) + fmaxf(b.y, 0.f),
                       fmaxf(a.z, 0.f) + fmaxf(b.z, 0.f),
                       fmaxf(a.w, 0.f) + fmaxf(b.w, 0.f));
}

// ---------------------------------------------------------------------------
// Gather: one warp per TASK (one list-pair) — perfectly balanced.
// ---------------------------------------------------------------------------
#define NTASKS 130000

__global__ void gather_kernel(float4* __restrict__ out) {
    int task = (blockIdx.x * blockDim.x + threadIdx.x) >> 5;
    int lane = threadIdx.x & 31;
    if (task >= NTASKS) return;

    const uint2* e1 = reinterpret_cast<const uint2*>(g_e1);
    const uint2* e2 = reinterpret_cast<const uint2*>(g_e2);

    float4 ha, hb;
    if (task < 50000) {                       // d-row, graph1
        int r = task;
        int n0 = min(g_cnt[r], CAP);
        int n1 = min(g_cnt[N1 + r], CAP);
        pair_accum(g_bkt1 + (size_t)r * CAP, n0,
                   g_bkt1 + (size_t)(N1 + r) * CAP, n1, e1, lane, ha, hb);
        float4 g = relu_add4(ha, hb);
        out[(size_t)(MEDNUM + r) * 32 + lane] =
            make_float4(2.f * g.x, 2.f * g.y, 2.f * g.z, 2.f * g.w);
    } else if (task < 90000) {                // p-row, graph2
        int r = task - 50000;
        int n0 = min(g_cnt[2 * N1 + r], CAP);
        int n1 = min(g_cnt[2 * N1 + N2 + r], CAP);
        pair_accum(g_bkt2 + (size_t)r * CAP, n0,
                   g_bkt2 + (size_t)(N2 + r) * CAP, n1, e2, lane, ha, hb);
        float4 g = relu_add4(ha, hb);
        out[(size_t)(MEDNUM + DIAGNUM + r) * 32 + lane] =
            make_float4(2.f * g.x, 2.f * g.y, 2.f * g.z, 2.f * g.w);
    } else if (task < 110000) {               // m-row, graph1 partial
        int m = task - 90000;
        int r = DIAGNUM + m;
        int n0 = min(g_cnt[r], CAP);
        int n1 = min(g_cnt[N1 + r], CAP);
        pair_accum(g_bkt1 + (size_t)r * CAP, n0,
                   g_bkt1 + (size_t)(N1 + r) * CAP, n1, e1, lane, ha, hb);
        reinterpret_cast<float4*>(g_mg1)[(size_t)m * 32 + lane] = relu_add4(ha, hb);
    } else {                                  // m-row, graph2 partial
        int m = task - 110000;
        int r = PRONUM + m;
        int n0 = min(g_cnt[2 * N1 + r], CAP);
        int n1 = min(g_cnt[2 * N1 + N2 + r], CAP);
        pair_accum(g_bkt2 + (size_t)r * CAP, n0,
                   g_bkt2 + (size_t)(N2 + r) * CAP, n1, e2, lane, ha, hb);
        reinterpret_cast<float4*>(g_mg2)[(size_t)m * 32 + lane] = relu_add4(ha, hb);
    }
}

// ---------------------------------------------------------------------------
// Blend the m-row partials: out[0..20000) = 2*(t*g1 + (1-t)*g2)
// ---------------------------------------------------------------------------
__global__ void m_combine_kernel(const float* __restrict__ inter,
                                 float4* __restrict__ out) {
    int i = blockIdx.x * blockDim.x + threadIdx.x;
    if (i >= MEDNUM * 32) return;
    float t = __ldg(inter);
    float u = 1.f - t;
    float4 a = reinterpret_cast<const float4*>(g_mg1)[i];
    float4 b = reinterpret_cast<const float4*>(g_mg2)[i];
    out[i] = make_float4(2.f * (t * a.x + u * b.x),
                         2.f * (t * a.y + u * b.y),
                         2.f * (t * a.z + u * b.z),
                         2.f * (t * a.w + u * b.w));
}

// ---------------------------------------------------------------------------
extern "C" void kernel_launch(void* const* d_in, const int* in_sizes, int n_in,
                              void* d_out, int out_size) {
    const int*   a1r = (const int*)d_in[0];
    const int*   a1c = (const int*)d_in[1];
    const float* a1v = (const float*)d_in[2];
    const int*   a2r = (const int*)d_in[3];
    const int*   a2c = (const int*)d_in[4];
    const float* a2v = (const float*)d_in[5];
    const float4* dE = (const float4*)d_in[6];
    const float4* mE = (const float4*)d_in[7];
    const float4* pE = (const float4*)d_in[8];
    const float* inter = (const float*)d_in[9];
    float4* out = (float4*)d_out;

    int2* bkt1;  cudaGetSymbolAddress((void**)&bkt1, g_bkt1);
    int2* bkt2;  cudaGetSymbolAddress((void**)&bkt2, g_bkt2);

    // 1. Zero counters
    {
        int threads = 256;
        int blocks = (NCNT + threads - 1) / threads;
        zero_cnt_kernel<<<blocks, threads>>>();
    }

    // 2. Convert embeddings to fp16 concatenated tables
    {
        int total = (N1 + N2) * FEATDIM / 4;
        int threads = 256;
        int blocks = (total + threads - 1) / threads;
        convert_kernel<<<blocks, threads>>>(dE, mE, pE);
    }

    // 3. Bucket all four adjacency lists in one launch
    {
        int total = 2 * NNZ1 + 2 * NNZ2;
        int threads = 256;
        int blocks = (total + threads - 1) / threads;
        bucket_kernel<<<blocks, threads>>>(a1r, a1c, a1v, a2r, a2c, a2v, bkt1, bkt2);
    }

    // 4. Balanced fused gather over fp16 tables
    {
        int threads = 256;
        int blocks = (NTASKS * 32 + threads - 1) / threads;
        gather_kernel<<<blocks, threads>>>(out);
    }

    // 5. Blend m-row partials
    {
        int threads = 256;
        int blocks = (MEDNUM * 32 + threads - 1) / threads;
        m_combine_kernel<<<blocks, threads>>>(inter, out);
    }
}

// round 9
// speedup vs baseline: 1.4661x; 1.3691x over previous
#include <cuda_runtime.h>
#include <cuda_fp16.h>
#include <cstdint>
#include <cstddef>

// Problem constants
#define DIAGNUM 50000
#define MEDNUM  20000
#define PRONUM  40000
#define FEATDIM 128
#define N1 (DIAGNUM + MEDNUM)   // 70000
#define N2 (PRONUM + MEDNUM)    // 60000
#define NNZ1 1120000
#define NNZ2 960000
#define CAP 64                  // Poisson(16): P(deg>64) ~ 1e-21 (clamped anyway)

#define NCNT (2 * N1 + 2 * N2)  // 260000 counters

__device__ int  g_cnt[NCNT];
__device__ int2 g_bkt1[(size_t)2 * N1 * CAP];      // graph1: lists 0,1
__device__ int2 g_bkt2[(size_t)2 * N2 * CAP];      // graph2: lists 0,1
__device__ float g_mg1[(size_t)MEDNUM * FEATDIM];  // m-row g1 partial
__device__ float g_mg2[(size_t)MEDNUM * FEATDIM];  // m-row g2 partial

// fp16 concatenated embedding tables
__device__ __half g_e1[(size_t)N1 * FEATDIM];      // [dEmbed | mEmbed] 17.9 MB
__device__ __half g_e2[(size_t)N2 * FEATDIM];      // [pEmbed | mEmbed] 15.4 MB

// ---------------------------------------------------------------------------
// Fused: zero counters + convert fp32 embeddings -> fp16 concatenated tables.
// One thread per float4 of table data; low threads also zero a counter.
// ---------------------------------------------------------------------------
__global__ void init_kernel(const float4* __restrict__ dE,
                            const float4* __restrict__ mE,
                            const float4* __restrict__ pE) {
    const int q1 = N1 * FEATDIM / 4;   // 2,240,000 float4 in e1
    const int q2 = N2 * FEATDIM / 4;   // 1,920,000 float4 in e2
    const int qd = DIAGNUM * FEATDIM / 4;
    const int qp = PRONUM * FEATDIM / 4;
    int i = blockIdx.x * blockDim.x + threadIdx.x;
    if (i < NCNT) g_cnt[i] = 0;
    if (i < q1) {
        float4 x = (i < qd) ? __ldg(dE + i) : __ldg(mE + (i - qd));
        __half2 lo = __floats2half2_rn(x.x, x.y);
        __half2 hi = __floats2half2_rn(x.z, x.w);
        uint2 packed;
        packed.x = *reinterpret_cast<unsigned*>(&lo);
        packed.y = *reinterpret_cast<unsigned*>(&hi);
        reinterpret_cast<uint2*>(g_e1)[i] = packed;
    } else {
        int j = i - q1;
        if (j >= q2) return;
        float4 x = (j < qp) ? __ldg(pE + j) : __ldg(mE + (j - qp));
        __half2 lo = __floats2half2_rn(x.x, x.y);
        __half2 hi = __floats2half2_rn(x.z, x.w);
        uint2 packed;
        packed.x = *reinterpret_cast<unsigned*>(&lo);
        packed.y = *reinterpret_cast<unsigned*>(&hi);
        reinterpret_cast<uint2*>(g_e2)[j] = packed;
    }
}

// ---------------------------------------------------------------------------
// Bucket scatter: one thread per edge, all four adjacency lists in one launch.
// ---------------------------------------------------------------------------
__global__ void bucket_kernel(const int* __restrict__ r1, const int* __restrict__ c1,
                              const float* __restrict__ v1,
                              const int* __restrict__ r2, const int* __restrict__ c2,
                              const float* __restrict__ v2,
                              int2* __restrict__ bkt1, int2* __restrict__ bkt2) {
    int idx = blockIdx.x * blockDim.x + threadIdx.x;
    if (idx < 2 * NNZ1) {
        int list = (idx >= NNZ1) ? 1 : 0;
        int r = __ldg(r1 + idx);
        int c = __ldg(c1 + idx);
        float v = __ldg(v1 + idx);
        int base = list * N1 + r;
        int slot = atomicAdd(&g_cnt[base], 1);
        if (slot < CAP)
            bkt1[(size_t)base * CAP + slot] = make_int2(c, __float_as_int(v));
    } else {
        int j = idx - 2 * NNZ1;
        if (j >= 2 * NNZ2) return;
        int list = (j >= NNZ2) ? 1 : 0;
        int r = __ldg(r2 + j);
        int c = __ldg(c2 + j);
        float v = __ldg(v2 + j);
        int base = list * N2 + r;
        int slot = atomicAdd(&g_cnt[2 * N1 + base], 1);
        if (slot < CAP)
            bkt2[(size_t)base * CAP + slot] = make_int2(c, __float_as_int(v));
    }
}

// ---------------------------------------------------------------------------
// Gather: one warp per TASK. Half-warp per adjacency list:
//   lanes 0-15  -> list 0,  lanes 16-31 -> list 1
// Each lane gathers uint4 = 16B = 8 fp16 features; 16 lanes cover the 256B row.
// One gather LDG serves TWO edges (one per half-warp).
// Branch-free padding: slot 0 re-read with value forced to 0.
// Final: relu per list, cross-half shfl-add, single coalesced STG.128/lane.
// ---------------------------------------------------------------------------
#define NTASKS 130000

__global__ void __launch_bounds__(256) gather_kernel(float4* __restrict__ out) {
    int task = (blockIdx.x * blockDim.x + threadIdx.x) >> 5;
    int lane = threadIdx.x & 31;
    if (task >= NTASKS) return;
    int half  = lane >> 4;          // which list this lane works on
    int hlane = lane & 15;          // feature chunk within the row

    // ---- task resolution (warp-uniform) ----
    const int2*  bktArr;
    const uint4* tbl;
    int b0, b1, cntBase;
    int outRow;          // >=0: final output row;  <0: m-partial index -(m+1)
    int isG1;
    if (task < 50000) {                         // d-row, graph1
        int r = task;
        bktArr = g_bkt1; tbl = reinterpret_cast<const uint4*>(g_e1);
        b0 = r; b1 = N1 + r; cntBase = 0;
        outRow = MEDNUM + r; isG1 = 1;
    } else if (task < 90000) {                  // p-row, graph2
        int r = task - 50000;
        bktArr = g_bkt2; tbl = reinterpret_cast<const uint4*>(g_e2);
        b0 = r; b1 = N2 + r; cntBase = 2 * N1;
        outRow = MEDNUM + DIAGNUM + r; isG1 = 0;
    } else if (task < 110000) {                 // m-row, graph1 partial
        int m = task - 90000;
        int r = DIAGNUM + m;
        bktArr = g_bkt1; tbl = reinterpret_cast<const uint4*>(g_e1);
        b0 = r; b1 = N1 + r; cntBase = 0;
        outRow = -(m + 1); isG1 = 1;
    } else {                                    // m-row, graph2 partial
        int m = task - 110000;
        int r = PRONUM + m;
        bktArr = g_bkt2; tbl = reinterpret_cast<const uint4*>(g_e2);
        b0 = r; b1 = N2 + r; cntBase = 2 * N1;
        outRow = -(m + 1); isG1 = 0;
    }

    int n0 = min(g_cnt[cntBase + b0], CAP);
    int n1 = min(g_cnt[cntBase + b1], CAP);
    int nmax = max(n0, n1);
    int nmy  = half ? n1 : n0;
    const int2* myBkt = bktArr + (size_t)(half ? b1 : b0) * CAP;

    float acc[8];
    #pragma unroll
    for (int i = 0; i < 8; i++) acc[i] = 0.f;

    for (int k = 0; k < nmax; k += 4) {
        // 4 edge loads (per half-warp broadcast), padded to slot 0
        int2 e[4];
        #pragma unroll
        for (int j = 0; j < 4; j++) {
            int kk = k + j;
            int idx = (kk < nmy) ? kk : 0;
            e[j] = __ldg(myBkt + idx);
        }
        // 4 gathers, each serving both half-warps (16B x 16 lanes = 256B row)
        uint4 x[4];
        float v[4];
        #pragma unroll
        for (int j = 0; j < 4; j++) {
            v[j] = (k + j < nmy) ? __int_as_float(e[j].y) : 0.f;
            x[j] = __ldg(tbl + (size_t)e[j].x * 16 + hlane);
        }
        // convert + accumulate (fp32)
        #pragma unroll
        for (int j = 0; j < 4; j++) {
            float2 f0 = __half22float2(*reinterpret_cast<__half2*>(&x[j].x));
            float2 f1 = __half22float2(*reinterpret_cast<__half2*>(&x[j].y));
            float2 f2 = __half22float2(*reinterpret_cast<__half2*>(&x[j].z));
            float2 f3 = __half22float2(*reinterpret_cast<__half2*>(&x[j].w));
            acc[0] = fmaf(v[j], f0.x, acc[0]);
            acc[1] = fmaf(v[j], f0.y, acc[1]);
            acc[2] = fmaf(v[j], f1.x, acc[2]);
            acc[3] = fmaf(v[j], f1.y, acc[3]);
            acc[4] = fmaf(v[j], f2.x, acc[4]);
            acc[5] = fmaf(v[j], f2.y, acc[5]);
            acc[6] = fmaf(v[j], f3.x, acc[6]);
            acc[7] = fmaf(v[j], f3.y, acc[7]);
        }
    }

    // relu per list, then add the other list's relu via cross-half shfl
    #pragma unroll
    for (int i = 0; i < 8; i++) acc[i] = fmaxf(acc[i], 0.f);
    #pragma unroll
    for (int i = 0; i < 8; i++) acc[i] += __shfl_xor_sync(0xffffffffu, acc[i], 16);

    // lane l (l<16) holds g chunk floats[8l..8l+8); lane 16+l holds the same.
    // lane l stores float4 #2l (lower half), lane 16+l stores #2l+1 (upper).
    float4 res = half ? make_float4(acc[4], acc[5], acc[6], acc[7])
                      : make_float4(acc[0], acc[1], acc[2], acc[3]);
    int f4idx = 2 * hlane + half;

    if (outRow >= 0) {
        res.x *= 2.f; res.y *= 2.f; res.z *= 2.f; res.w *= 2.f;
        out[(size_t)outRow * 32 + f4idx] = res;
    } else {
        int m = -outRow - 1;
        float4* scr = reinterpret_cast<float4*>(isG1 ? g_mg1 : g_mg2);
        scr[(size_t)m * 32 + f4idx] = res;
    }
}

// ---------------------------------------------------------------------------
// Blend the m-row partials: out[0..20000) = 2*(t*g1 + (1-t)*g2)
// ---------------------------------------------------------------------------
__global__ void m_combine_kernel(const float* __restrict__ inter,
                                 float4* __restrict__ out) {
    int i = blockIdx.x * blockDim.x + threadIdx.x;
    if (i >= MEDNUM * 32) return;
    float t = __ldg(inter);
    float u = 1.f - t;
    float4 a = reinterpret_cast<const float4*>(g_mg1)[i];
    float4 b = reinterpret_cast<const float4*>(g_mg2)[i];
    out[i] = make_float4(2.f * (t * a.x + u * b.x),
                         2.f * (t * a.y + u * b.y),
                         2.f * (t * a.z + u * b.z),
                         2.f * (t * a.w + u * b.w));
}

// ---------------------------------------------------------------------------
extern "C" void kernel_launch(void* const* d_in, const int* in_sizes, int n_in,
                              void* d_out, int out_size) {
    const int*   a1r = (const int*)d_in[0];
    const int*   a1c = (const int*)d_in[1];
    const float* a1v = (const float*)d_in[2];
    const int*   a2r = (const int*)d_in[3];
    const int*   a2c = (const int*)d_in[4];
    const float* a2v = (const float*)d_in[5];
    const float4* dE = (const float4*)d_in[6];
    const float4* mE = (const float4*)d_in[7];
    const float4* pE = (const float4*)d_in[8];
    const float* inter = (const float*)d_in[9];
    float4* out = (float4*)d_out;

    int2* bkt1;  cudaGetSymbolAddress((void**)&bkt1, g_bkt1);
    int2* bkt2;  cudaGetSymbolAddress((void**)&bkt2, g_bkt2);

    // 1. Fused: zero counters + fp16 table conversion
    {
        int total = (N1 + N2) * FEATDIM / 4;   // > NCNT
        int threads = 256;
        int blocks = (total + threads - 1) / threads;
        init_kernel<<<blocks, threads>>>(dE, mE, pE);
    }

    // 2. Bucket all four adjacency lists in one launch
    {
        int total = 2 * NNZ1 + 2 * NNZ2;
        int threads = 256;
        int blocks = (total + threads - 1) / threads;
        bucket_kernel<<<blocks, threads>>>(a1r, a1c, a1v, a2r, a2c, a2v, bkt1, bkt2);
    }

    // 3. Half-warp-per-list fused gather
    {
        int threads = 256;
        int blocks = (NTASKS * 32 + threads - 1) / threads;
        gather_kernel<<<blocks, threads>>>(out);
    }

    // 4. Blend m-row partials
    {
        int threads = 256;
        int blocks = (MEDNUM * 32 + threads - 1) / threads;
        m_combine_kernel<<<blocks, threads>>>(inter, out);
    }
}

// round 11
// speedup vs baseline: 1.4712x; 1.0034x over previous
#include <cuda_runtime.h>
#include <cuda_fp16.h>
#include <cstdint>
#include <cstddef>

// Problem constants
#define DIAGNUM 50000
#define MEDNUM  20000
#define PRONUM  40000
#define FEATDIM 128
#define N1 (DIAGNUM + MEDNUM)   // 70000
#define N2 (PRONUM + MEDNUM)    // 60000
#define NNZ1 1120000
#define NNZ2 960000
#define CAP 64                  // Poisson(16): P(deg>64) ~ 1e-21 (clamped anyway)

#define NCNT (2 * N1 + 2 * N2)  // 260000 counters

__device__ int  g_cnt[NCNT];
__device__ int2 g_bkt1[(size_t)2 * N1 * CAP];      // graph1: lists 0,1
__device__ int2 g_bkt2[(size_t)2 * N2 * CAP];      // graph2: lists 0,1

// fp16 concatenated embedding tables
__device__ __half g_e1[(size_t)N1 * FEATDIM];      // [dEmbed | mEmbed] 17.9 MB
__device__ __half g_e2[(size_t)N2 * FEATDIM];      // [pEmbed | mEmbed] 15.4 MB

// ---------------------------------------------------------------------------
// Fused init: zero counters + zero out's m-region (rows [0,MEDNUM), receives
// red.add) + convert fp32 embeddings -> fp16 concatenated tables.
// ---------------------------------------------------------------------------
__global__ void init_kernel(const float4* __restrict__ dE,
                            const float4* __restrict__ mE,
                            const float4* __restrict__ pE,
                            float4* __restrict__ out) {
    const int q1 = N1 * FEATDIM / 4;   // 2,240,000 float4 in e1
    const int q2 = N2 * FEATDIM / 4;   // 1,920,000 float4 in e2
    const int qd = DIAGNUM * FEATDIM / 4;
    const int qp = PRONUM * FEATDIM / 4;
    const int qm = MEDNUM * FEATDIM / 4;  // 640,000 float4 in out m-region
    int i = blockIdx.x * blockDim.x + threadIdx.x;
    if (i < NCNT) g_cnt[i] = 0;
    if (i < qm) out[i] = make_float4(0.f, 0.f, 0.f, 0.f);
    if (i < q1) {
        float4 x = (i < qd) ? __ldg(dE + i) : __ldg(mE + (i - qd));
        __half2 lo = __floats2half2_rn(x.x, x.y);
        __half2 hi = __floats2half2_rn(x.z, x.w);
        uint2 packed;
        packed.x = *reinterpret_cast<unsigned*>(&lo);
        packed.y = *reinterpret_cast<unsigned*>(&hi);
        reinterpret_cast<uint2*>(g_e1)[i] = packed;
    } else {
        int j = i - q1;
        if (j >= q2) return;
        float4 x = (j < qp) ? __ldg(pE + j) : __ldg(mE + (j - qp));
        __half2 lo = __floats2half2_rn(x.x, x.y);
        __half2 hi = __floats2half2_rn(x.z, x.w);
        uint2 packed;
        packed.x = *reinterpret_cast<unsigned*>(&lo);
        packed.y = *reinterpret_cast<unsigned*>(&hi);
        reinterpret_cast<uint2*>(g_e2)[j] = packed;
    }
}

// ---------------------------------------------------------------------------
// Bucket scatter: TWO edges per thread via int2/float2 loads (arrays are
// (2,NNZ) contiguous; NNZ even => an aligned pair never straddles lists).
// ---------------------------------------------------------------------------
__global__ void bucket_kernel(const int* __restrict__ r1, const int* __restrict__ c1,
                              const float* __restrict__ v1,
                              const int* __restrict__ r2, const int* __restrict__ c2,
                              const float* __restrict__ v2,
                              int2* __restrict__ bkt1, int2* __restrict__ bkt2) {
    int tid = blockIdx.x * blockDim.x + threadIdx.x;
    if (tid < NNZ1) {                               // graph1 pair at e = 2*tid
        int e = 2 * tid;
        int list = (e >= NNZ1) ? 1 : 0;
        int2   r = __ldg(reinterpret_cast<const int2*>(r1) + tid);
        int2   c = __ldg(reinterpret_cast<const int2*>(c1) + tid);
        float2 v = __ldg(reinterpret_cast<const float2*>(v1) + tid);
        int base0 = list * N1 + r.x;
        int base1 = list * N1 + r.y;
        int s0 = atomicAdd(&g_cnt[base0], 1);
        int s1 = atomicAdd(&g_cnt[base1], 1);
        if (s0 < CAP) bkt1[(size_t)base0 * CAP + s0] = make_int2(c.x, __float_as_int(v.x));
        if (s1 < CAP) bkt1[(size_t)base1 * CAP + s1] = make_int2(c.y, __float_as_int(v.y));
    } else {                                        // graph2 pair
        int p = tid - NNZ1;
        if (p >= NNZ2) return;
        int e = 2 * p;
        int list = (e >= NNZ2) ? 1 : 0;
        int2   r = __ldg(reinterpret_cast<const int2*>(r2) + p);
        int2   c = __ldg(reinterpret_cast<const int2*>(c2) + p);
        float2 v = __ldg(reinterpret_cast<const float2*>(v2) + p);
        int base0 = 2 * N1 + list * N2 + r.x;
        int base1 = 2 * N1 + list * N2 + r.y;
        int s0 = atomicAdd(&g_cnt[base0], 1);
        int s1 = atomicAdd(&g_cnt[base1], 1);
        if (s0 < CAP) bkt2[(size_t)(base0 - 2 * N1) * CAP + s0] = make_int2(c.x, __float_as_int(v.x));
        if (s1 < CAP) bkt2[(size_t)(base1 - 2 * N1) * CAP + s1] = make_int2(c.y, __float_as_int(v.y));
    }
}

// ---------------------------------------------------------------------------
// Gather: one warp per TASK. Half-warp per adjacency list (lanes 0-15 list0,
// 16-31 list1); lane gathers uint4 = 8 fp16 features; 16 lanes = 256B row.
// d/p tasks: plain store. m tasks: red.global.add.v4 into out with blend
// factor folded in (2t for g1, 2(1-t) for g2) — no scratch, no combine pass.
// ---------------------------------------------------------------------------
#define NTASKS 130000

__global__ void __launch_bounds__(256) gather_kernel(const float* __restrict__ inter,
                                                     float4* __restrict__ out) {
    int task = (blockIdx.x * blockDim.x + threadIdx.x) >> 5;
    int lane = threadIdx.x & 31;
    if (task >= NTASKS) return;
    int half  = lane >> 4;
    int hlane = lane & 15;

    // ---- task resolution (warp-uniform) ----
    const int2*  bktArr;
    const uint4* tbl;
    int b0, b1, cntBase;
    int outRow;           // output row in out
    int mMode;            // 0: plain store (factor 2), 1: red.add with factor f
    float f = 2.f;
    if (task < 50000) {                         // d-row, graph1
        int r = task;
        bktArr = g_bkt1; tbl = reinterpret_cast<const uint4*>(g_e1);
        b0 = r; b1 = N1 + r; cntBase = 0;
        outRow = MEDNUM + r; mMode = 0;
    } else if (task < 90000) {                  // p-row, graph2
        int r = task - 50000;
        bktArr = g_bkt2; tbl = reinterpret_cast<const uint4*>(g_e2);
        b0 = r; b1 = N2 + r; cntBase = 2 * N1;
        outRow = MEDNUM + DIAGNUM + r; mMode = 0;
    } else if (task < 110000) {                 // m-row, graph1 -> +2t*relu
        int m = task - 90000;
        int r = DIAGNUM + m;
        bktArr = g_bkt1; tbl = reinterpret_cast<const uint4*>(g_e1);
        b0 = r; b1 = N1 + r; cntBase = 0;
        outRow = m; mMode = 1;
        f = 2.f * __ldg(inter);
    } else {                                    // m-row, graph2 -> +2(1-t)*relu
        int m = task - 110000;
        int r = PRONUM + m;
        bktArr = g_bkt2; tbl = reinterpret_cast<const uint4*>(g_e2);
        b0 = r; b1 = N2 + r; cntBase = 2 * N1;
        outRow = m; mMode = 1;
        f = 2.f * (1.f - __ldg(inter));
    }

    int n0 = min(g_cnt[cntBase + b0], CAP);
    int n1 = min(g_cnt[cntBase + b1], CAP);
    int nmax = max(n0, n1);
    int nmy  = half ? n1 : n0;
    const int2* myBkt = bktArr + (size_t)(half ? b1 : b0) * CAP;

    float acc[8];
    #pragma unroll
    for (int i = 0; i < 8; i++) acc[i] = 0.f;

    for (int k = 0; k < nmax; k += 4) {
        int2 e[4];
        #pragma unroll
        for (int j = 0; j < 4; j++) {
            int kk = k + j;
            int idx = (kk < nmy) ? kk : 0;      // pad to slot 0 (always valid)
            e[j] = __ldg(myBkt + idx);
        }
        uint4 x[4];
        float v[4];
        #pragma unroll
        for (int j = 0; j < 4; j++) {
            v[j] = (k + j < nmy) ? __int_as_float(e[j].y) : 0.f;
            x[j] = __ldg(tbl + (size_t)e[j].x * 16 + hlane);
        }
        #pragma unroll
        for (int j = 0; j < 4; j++) {
            float2 f0 = __half22float2(*reinterpret_cast<__half2*>(&x[j].x));
            float2 f1 = __half22float2(*reinterpret_cast<__half2*>(&x[j].y));
            float2 f2 = __half22float2(*reinterpret_cast<__half2*>(&x[j].z));
            float2 f3 = __half22float2(*reinterpret_cast<__half2*>(&x[j].w));
            acc[0] = fmaf(v[j], f0.x, acc[0]);
            acc[1] = fmaf(v[j], f0.y, acc[1]);
            acc[2] = fmaf(v[j], f1.x, acc[2]);
            acc[3] = fmaf(v[j], f1.y, acc[3]);
            acc[4] = fmaf(v[j], f2.x, acc[4]);
            acc[5] = fmaf(v[j], f2.y, acc[5]);
            acc[6] = fmaf(v[j], f3.x, acc[6]);
            acc[7] = fmaf(v[j], f3.y, acc[7]);
        }
    }

    // relu per list, cross-half add => g = relu(h0)+relu(h1) in both halves
    #pragma unroll
    for (int i = 0; i < 8; i++) acc[i] = fmaxf(acc[i], 0.f);
    #pragma unroll
    for (int i = 0; i < 8; i++) acc[i] += __shfl_xor_sync(0xffffffffu, acc[i], 16);

    float4 res = half ? make_float4(acc[4], acc[5], acc[6], acc[7])
                      : make_float4(acc[0], acc[1], acc[2], acc[3]);
    res.x *= f; res.y *= f; res.z *= f; res.w *= f;
    float4* dst = out + (size_t)outRow * 32 + 2 * hlane + half;

    if (mMode == 0) {
        *dst = res;
    } else {
        asm volatile("red.global.add.v4.f32 [%0], {%1, %2, %3, %4};"
                     :: "l"(dst), "f"(res.x), "f"(res.y), "f"(res.z), "f"(res.w)
                     : "memory");
    }
}

// ---------------------------------------------------------------------------
extern "C" void kernel_launch(void* const* d_in, const int* in_sizes, int n_in,
                              void* d_out, int out_size) {
    const int*   a1r = (const int*)d_in[0];
    const int*   a1c = (const int*)d_in[1];
    const float* a1v = (const float*)d_in[2];
    const int*   a2r = (const int*)d_in[3];
    const int*   a2c = (const int*)d_in[4];
    const float* a2v = (const float*)d_in[5];
    const float4* dE = (const float4*)d_in[6];
    const float4* mE = (const float4*)d_in[7];
    const float4* pE = (const float4*)d_in[8];
    const float* inter = (const float*)d_in[9];
    float4* out = (float4*)d_out;

    int2* bkt1;  cudaGetSymbolAddress((void**)&bkt1, g_bkt1);
    int2* bkt2;  cudaGetSymbolAddress((void**)&bkt2, g_bkt2);

    // 1. Fused init: zero counters + zero out m-region + fp16 tables
    {
        int total = (N1 + N2) * FEATDIM / 4;
        int threads = 256;
        int blocks = (total + threads - 1) / threads;
        init_kernel<<<blocks, threads>>>(dE, mE, pE, out);
    }

    // 2. Bucket all four adjacency lists, 2 edges/thread
    {
        int totalPairs = NNZ1 + NNZ2;
        int threads = 256;
        int blocks = (totalPairs + threads - 1) / threads;
        bucket_kernel<<<blocks, threads>>>(a1r, a1c, a1v, a2r, a2c, a2v, bkt1, bkt2);
    }

    // 3. Half-warp-per-list fused gather (m rows blended via red.add)
    {
        int threads = 256;
        int blocks = (NTASKS * 32 + threads - 1) / threads;
        gather_kernel<<<blocks, threads>>>(inter, out);
    }
}

// round 12
// speedup vs baseline: 1.4833x; 1.0082x over previous
#include <cuda_runtime.h>
#include <cuda_fp16.h>
#include <cstdint>
#include <cstddef>

// Problem constants
#define DIAGNUM 50000
#define MEDNUM  20000
#define PRONUM  40000
#define FEATDIM 128
#define N1 (DIAGNUM + MEDNUM)   // 70000
#define N2 (PRONUM + MEDNUM)    // 60000
#define NNZ1 1120000
#define NNZ2 960000
#define CAP 64                  // Poisson(16): P(deg>64) ~ 1e-21 (clamped anyway)

#define NCNT (2 * N1 + 2 * N2)  // 260000 counters

__device__ int  g_cnt[NCNT];
__device__ int2 g_bkt1[(size_t)2 * N1 * CAP];      // graph1: lists 0,1
__device__ int2 g_bkt2[(size_t)2 * N2 * CAP];      // graph2: lists 0,1

// fp16 concatenated embedding tables
__device__ __half g_e1[(size_t)N1 * FEATDIM];      // [dEmbed | mEmbed] 17.9 MB
__device__ __half g_e2[(size_t)N2 * FEATDIM];      // [pEmbed | mEmbed] 15.4 MB

// ---------------------------------------------------------------------------
// Fused init: zero counters + zero out's m-region (rows [0,MEDNUM), receives
// red.add) + convert fp32 embeddings -> fp16 concatenated tables.
// ---------------------------------------------------------------------------
__global__ void init_kernel(const float4* __restrict__ dE,
                            const float4* __restrict__ mE,
                            const float4* __restrict__ pE,
                            float4* __restrict__ out) {
    const int q1 = N1 * FEATDIM / 4;   // 2,240,000 float4 in e1
    const int q2 = N2 * FEATDIM / 4;   // 1,920,000 float4 in e2
    const int qd = DIAGNUM * FEATDIM / 4;
    const int qp = PRONUM * FEATDIM / 4;
    const int qm = MEDNUM * FEATDIM / 4;  // 640,000 float4 in out m-region
    int i = blockIdx.x * blockDim.x + threadIdx.x;
    if (i < NCNT) g_cnt[i] = 0;
    if (i < qm) out[i] = make_float4(0.f, 0.f, 0.f, 0.f);
    if (i < q1) {
        float4 x = (i < qd) ? __ldg(dE + i) : __ldg(mE + (i - qd));
        __half2 lo = __floats2half2_rn(x.x, x.y);
        __half2 hi = __floats2half2_rn(x.z, x.w);
        uint2 packed;
        packed.x = *reinterpret_cast<unsigned*>(&lo);
        packed.y = *reinterpret_cast<unsigned*>(&hi);
        reinterpret_cast<uint2*>(g_e1)[i] = packed;
    } else {
        int j = i - q1;
        if (j >= q2) return;
        float4 x = (j < qp) ? __ldg(pE + j) : __ldg(mE + (j - qp));
        __half2 lo = __floats2half2_rn(x.x, x.y);
        __half2 hi = __floats2half2_rn(x.z, x.w);
        uint2 packed;
        packed.x = *reinterpret_cast<unsigned*>(&lo);
        packed.y = *reinterpret_cast<unsigned*>(&hi);
        reinterpret_cast<uint2*>(g_e2)[j] = packed;
    }
}

// ---------------------------------------------------------------------------
// Bucket scatter: TWO edges per thread via int2/float2 loads (arrays are
// (2,NNZ) contiguous; NNZ even => an aligned pair never straddles lists).
// ---------------------------------------------------------------------------
__global__ void bucket_kernel(const int* __restrict__ r1, const int* __restrict__ c1,
                              const float* __restrict__ v1,
                              const int* __restrict__ r2, const int* __restrict__ c2,
                              const float* __restrict__ v2,
                              int2* __restrict__ bkt1, int2* __restrict__ bkt2) {
    int tid = blockIdx.x * blockDim.x + threadIdx.x;
    if (tid < NNZ1) {                               // graph1 pair at e = 2*tid
        int e = 2 * tid;
        int list = (e >= NNZ1) ? 1 : 0;
        int2   r = __ldg(reinterpret_cast<const int2*>(r1) + tid);
        int2   c = __ldg(reinterpret_cast<const int2*>(c1) + tid);
        float2 v = __ldg(reinterpret_cast<const float2*>(v1) + tid);
        int base0 = list * N1 + r.x;
        int base1 = list * N1 + r.y;
        int s0 = atomicAdd(&g_cnt[base0], 1);
        int s1 = atomicAdd(&g_cnt[base1], 1);
        if (s0 < CAP) bkt1[(size_t)base0 * CAP + s0] = make_int2(c.x, __float_as_int(v.x));
        if (s1 < CAP) bkt1[(size_t)base1 * CAP + s1] = make_int2(c.y, __float_as_int(v.y));
    } else {                                        // graph2 pair
        int p = tid - NNZ1;
        if (p >= NNZ2) return;
        int e = 2 * p;
        int list = (e >= NNZ2) ? 1 : 0;
        int2   r = __ldg(reinterpret_cast<const int2*>(r2) + p);
        int2   c = __ldg(reinterpret_cast<const int2*>(c2) + p);
        float2 v = __ldg(reinterpret_cast<const float2*>(v2) + p);
        int base0 = 2 * N1 + list * N2 + r.x;
        int base1 = 2 * N1 + list * N2 + r.y;
        int s0 = atomicAdd(&g_cnt[base0], 1);
        int s1 = atomicAdd(&g_cnt[base1], 1);
        if (s0 < CAP) bkt2[(size_t)(base0 - 2 * N1) * CAP + s0] = make_int2(c.x, __float_as_int(v.x));
        if (s1 < CAP) bkt2[(size_t)(base1 - 2 * N1) * CAP + s1] = make_int2(c.y, __float_as_int(v.y));
    }
}

// ---------------------------------------------------------------------------
// Gather: one warp per TASK. Half-warp per adjacency list (lanes 0-15 list0,
// 16-31 list1); lane gathers uint4 = 8 fp16 features; 16 lanes = 256B row.
// d/p tasks: plain store. m tasks: red.global.add.v4 into out with blend
// factor folded in (2t for g1, 2(1-t) for g2) — no scratch, no combine pass.
// ---------------------------------------------------------------------------
#define NTASKS 130000

__global__ void __launch_bounds__(256) gather_kernel(const float* __restrict__ inter,
                                                     float4* __restrict__ out) {
    int task = (blockIdx.x * blockDim.x + threadIdx.x) >> 5;
    int lane = threadIdx.x & 31;
    if (task >= NTASKS) return;
    int half  = lane >> 4;
    int hlane = lane & 15;

    // ---- task resolution (warp-uniform) ----
    const int2*  bktArr;
    const uint4* tbl;
    int b0, b1, cntBase;
    int outRow;           // output row in out
    int mMode;            // 0: plain store (factor 2), 1: red.add with factor f
    float f = 2.f;
    if (task < 50000) {                         // d-row, graph1
        int r = task;
        bktArr = g_bkt1; tbl = reinterpret_cast<const uint4*>(g_e1);
        b0 = r; b1 = N1 + r; cntBase = 0;
        outRow = MEDNUM + r; mMode = 0;
    } else if (task < 90000) {                  // p-row, graph2
        int r = task - 50000;
        bktArr = g_bkt2; tbl = reinterpret_cast<const uint4*>(g_e2);
        b0 = r; b1 = N2 + r; cntBase = 2 * N1;
        outRow = MEDNUM + DIAGNUM + r; mMode = 0;
    } else if (task < 110000) {                 // m-row, graph1 -> +2t*relu
        int m = task - 90000;
        int r = DIAGNUM + m;
        bktArr = g_bkt1; tbl = reinterpret_cast<const uint4*>(g_e1);
        b0 = r; b1 = N1 + r; cntBase = 0;
        outRow = m; mMode = 1;
        f = 2.f * __ldg(inter);
    } else {                                    // m-row, graph2 -> +2(1-t)*relu
        int m = task - 110000;
        int r = PRONUM + m;
        bktArr = g_bkt2; tbl = reinterpret_cast<const uint4*>(g_e2);
        b0 = r; b1 = N2 + r; cntBase = 2 * N1;
        outRow = m; mMode = 1;
        f = 2.f * (1.f - __ldg(inter));
    }

    int n0 = min(g_cnt[cntBase + b0], CAP);
    int n1 = min(g_cnt[cntBase + b1], CAP);
    int nmax = max(n0, n1);
    int nmy  = half ? n1 : n0;
    const int2* myBkt = bktArr + (size_t)(half ? b1 : b0) * CAP;

    float acc[8];
    #pragma unroll
    for (int i = 0; i < 8; i++) acc[i] = 0.f;

    for (int k = 0; k < nmax; k += 4) {
        int2 e[4];
        #pragma unroll
        for (int j = 0; j < 4; j++) {
            int kk = k + j;
            int idx = (kk < nmy) ? kk : 0;      // pad to slot 0 (always valid)
            e[j] = __ldg(myBkt + idx);
        }
        uint4 x[4];
        float v[4];
        #pragma unroll
        for (int j = 0; j < 4; j++) {
            v[j] = (k + j < nmy) ? __int_as_float(e[j].y) : 0.f;
            x[j] = __ldg(tbl + (size_t)e[j].x * 16 + hlane);
        }
        #pragma unroll
        for (int j = 0; j < 4; j++) {
            float2 f0 = __half22float2(*reinterpret_cast<__half2*>(&x[j].x));
            float2 f1 = __half22float2(*reinterpret_cast<__half2*>(&x[j].y));
            float2 f2 = __half22float2(*reinterpret_cast<__half2*>(&x[j].z));
            float2 f3 = __half22float2(*reinterpret_cast<__half2*>(&x[j].w));
            acc[0] = fmaf(v[j], f0.x, acc[0]);
            acc[1] = fmaf(v[j], f0.y, acc[1]);
            acc[2] = fmaf(v[j], f1.x, acc[2]);
            acc[3] = fmaf(v[j], f1.y, acc[3]);
            acc[4] = fmaf(v[j], f2.x, acc[4]);
            acc[5] = fmaf(v[j], f2.y, acc[5]);
            acc[6] = fmaf(v[j], f3.x, acc[6]);
            acc[7] = fmaf(v[j], f3.y, acc[7]);
        }
    }

    // relu per list, cross-half add => g = relu(h0)+relu(h1) in both halves
    #pragma unroll
    for (int i = 0; i < 8; i++) acc[i] = fmaxf(acc[i], 0.f);
    #pragma unroll
    for (int i = 0; i < 8; i++) acc[i] += __shfl_xor_sync(0xffffffffu, acc[i], 16);

    float4 res = half ? make_float4(acc[4], acc[5], acc[6], acc[7])
                      : make_float4(acc[0], acc[1], acc[2], acc[3]);
    res.x *= f; res.y *= f; res.z *= f; res.w *= f;
    float4* dst = out + (size_t)outRow * 32 + 2 * hlane + half;

    if (mMode == 0) {
        *dst = res;
    } else {
        asm volatile("red.global.add.v4.f32 [%0], {%1, %2, %3, %4};"
                     :: "l"(dst), "f"(res.x), "f"(res.y), "f"(res.z), "f"(res.w)
                     : "memory");
    }
}

// ---------------------------------------------------------------------------
extern "C" void kernel_launch(void* const* d_in, const int* in_sizes, int n_in,
                              void* d_out, int out_size) {
    const int*   a1r = (const int*)d_in[0];
    const int*   a1c = (const int*)d_in[1];
    const float* a1v = (const float*)d_in[2];
    const int*   a2r = (const int*)d_in[3];
    const int*   a2c = (const int*)d_in[4];
    const float* a2v = (const float*)d_in[5];
    const float4* dE = (const float4*)d_in[6];
    const float4* mE = (const float4*)d_in[7];
    const float4* pE = (const float4*)d_in[8];
    const float* inter = (const float*)d_in[9];
    float4* out = (float4*)d_out;

    int2* bkt1;  cudaGetSymbolAddress((void**)&bkt1, g_bkt1);
    int2* bkt2;  cudaGetSymbolAddress((void**)&bkt2, g_bkt2);

    // 1. Fused init: zero counters + zero out m-region + fp16 tables
    {
        int total = (N1 + N2) * FEATDIM / 4;
        int threads = 256;
        int blocks = (total + threads - 1) / threads;
        init_kernel<<<blocks, threads>>>(dE, mE, pE, out);
    }

    // 2. Bucket all four adjacency lists, 2 edges/thread
    {
        int totalPairs = NNZ1 + NNZ2;
        int threads = 256;
        int blocks = (totalPairs + threads - 1) / threads;
        bucket_kernel<<<blocks, threads>>>(a1r, a1c, a1v, a2r, a2c, a2v, bkt1, bkt2);
    }

    // 3. Half-warp-per-list fused gather (m rows blended via red.add)
    {
        int threads = 256;
        int blocks = (NTASKS * 32 + threads - 1) / threads;
        gather_kernel<<<blocks, threads>>>(inter, out);
    }
}

// round 13
// speedup vs baseline: 1.5286x; 1.0306x over previous
#include <cuda_runtime.h>
#include <cuda_fp16.h>
#include <cstdint>
#include <cstddef>

// Problem constants
#define DIAGNUM 50000
#define MEDNUM  20000
#define PRONUM  40000
#define FEATDIM 128
#define N1 (DIAGNUM + MEDNUM)   // 70000
#define N2 (PRONUM + MEDNUM)    // 60000
#define NNZ1 1120000
#define NNZ2 960000
#define CAP 64                  // Poisson(16): P(deg>64) ~ 1e-21 (clamped anyway)

#define NCNT (2 * N1 + 2 * N2)  // 260000 counters

__device__ int  g_cnt[NCNT];
__device__ int2 g_bkt1[(size_t)2 * N1 * CAP];      // graph1: lists 0,1
__device__ int2 g_bkt2[(size_t)2 * N2 * CAP];      // graph2: lists 0,1

// fp16 concatenated embedding tables
__device__ __half g_e1[(size_t)N1 * FEATDIM];      // [dEmbed | mEmbed] 17.9 MB
__device__ __half g_e2[(size_t)N2 * FEATDIM];      // [pEmbed | mEmbed] 15.4 MB

// ---------------------------------------------------------------------------
// Zero counters (tiny, ~1 MB)
// ---------------------------------------------------------------------------
__global__ void zero_cnt_kernel() {
    int i = blockIdx.x * blockDim.x + threadIdx.x;
    if (i < NCNT) g_cnt[i] = 0;
}

// ---------------------------------------------------------------------------
// Fused bucket + convert. Blocks [0, bucketBlocks) do edge bucketing
// (2 edges/thread, atomic-latency-bound); remaining blocks do the fp32->fp16
// table conversion (bandwidth-bound). The two co-reside on SMs => overlap.
// ---------------------------------------------------------------------------
#define BUCKET_THREADS 256
#define BUCKET_BLOCKS ((NNZ1 + NNZ2 + BUCKET_THREADS - 1) / BUCKET_THREADS)   // 8125
#define CONV_TOTAL ((N1 + N2) * FEATDIM / 4)                                  // 4,160,000
#define CONV_BLOCKS ((CONV_TOTAL + BUCKET_THREADS - 1) / BUCKET_THREADS)      // 16250

__global__ void prep_kernel(const int* __restrict__ r1, const int* __restrict__ c1,
                            const float* __restrict__ v1,
                            const int* __restrict__ r2, const int* __restrict__ c2,
                            const float* __restrict__ v2,
                            int2* __restrict__ bkt1, int2* __restrict__ bkt2,
                            const float4* __restrict__ dE,
                            const float4* __restrict__ mE,
                            const float4* __restrict__ pE) {
    if (blockIdx.x < BUCKET_BLOCKS) {
        // ------- bucket scatter: two edges per thread -------
        int tid = blockIdx.x * blockDim.x + threadIdx.x;
        if (tid < NNZ1) {                           // graph1 pair at e = 2*tid
            int e = 2 * tid;
            int list = (e >= NNZ1) ? 1 : 0;
            int2   r = __ldg(reinterpret_cast<const int2*>(r1) + tid);
            int2   c = __ldg(reinterpret_cast<const int2*>(c1) + tid);
            float2 v = __ldg(reinterpret_cast<const float2*>(v1) + tid);
            int base0 = list * N1 + r.x;
            int base1 = list * N1 + r.y;
            int s0 = atomicAdd(&g_cnt[base0], 1);
            int s1 = atomicAdd(&g_cnt[base1], 1);
            if (s0 < CAP) bkt1[(size_t)base0 * CAP + s0] = make_int2(c.x, __float_as_int(v.x));
            if (s1 < CAP) bkt1[(size_t)base1 * CAP + s1] = make_int2(c.y, __float_as_int(v.y));
        } else {                                    // graph2 pair
            int p = tid - NNZ1;
            if (p >= NNZ2) return;
            int e = 2 * p;
            int list = (e >= NNZ2) ? 1 : 0;
            int2   r = __ldg(reinterpret_cast<const int2*>(r2) + p);
            int2   c = __ldg(reinterpret_cast<const int2*>(c2) + p);
            float2 v = __ldg(reinterpret_cast<const float2*>(v2) + p);
            int base0 = list * N2 + r.x;
            int base1 = list * N2 + r.y;
            int s0 = atomicAdd(&g_cnt[2 * N1 + base0], 1);
            int s1 = atomicAdd(&g_cnt[2 * N1 + base1], 1);
            if (s0 < CAP) bkt2[(size_t)base0 * CAP + s0] = make_int2(c.x, __float_as_int(v.x));
            if (s1 < CAP) bkt2[(size_t)base1 * CAP + s1] = make_int2(c.y, __float_as_int(v.y));
        }
    } else {
        // ------- fp32 -> fp16 table conversion -------
        const int q1 = N1 * FEATDIM / 4;
        const int q2 = N2 * FEATDIM / 4;
        const int qd = DIAGNUM * FEATDIM / 4;
        const int qp = PRONUM * FEATDIM / 4;
        int i = (blockIdx.x - BUCKET_BLOCKS) * blockDim.x + threadIdx.x;
        if (i < q1) {
            float4 x = (i < qd) ? __ldg(dE + i) : __ldg(mE + (i - qd));
            __half2 lo = __floats2half2_rn(x.x, x.y);
            __half2 hi = __floats2half2_rn(x.z, x.w);
            uint2 packed;
            packed.x = *reinterpret_cast<unsigned*>(&lo);
            packed.y = *reinterpret_cast<unsigned*>(&hi);
            reinterpret_cast<uint2*>(g_e1)[i] = packed;
        } else {
            int j = i - q1;
            if (j >= q2) return;
            float4 x = (j < qp) ? __ldg(pE + j) : __ldg(mE + (j - qp));
            __half2 lo = __floats2half2_rn(x.x, x.y);
            __half2 hi = __floats2half2_rn(x.z, x.w);
            uint2 packed;
            packed.x = *reinterpret_cast<unsigned*>(&lo);
            packed.y = *reinterpret_cast<unsigned*>(&hi);
            reinterpret_cast<uint2*>(g_e2)[j] = packed;
        }
    }
}

// ---------------------------------------------------------------------------
// Core: accumulate one list-pair (half-warp per list), relu both, cross-half
// add => every lane holds g = relu(h0)+relu(h1) for its feature chunk.
// ---------------------------------------------------------------------------
__device__ __forceinline__ void pair_core(const int2* __restrict__ bktArr,
                                          int b0, int b1, int cntBase,
                                          const uint4* __restrict__ tbl,
                                          int half, int hlane, float acc[8]) {
    int n0 = min(g_cnt[cntBase + b0], CAP);
    int n1 = min(g_cnt[cntBase + b1], CAP);
    int nmax = max(n0, n1);
    int nmy  = half ? n1 : n0;
    const int2* myBkt = bktArr + (size_t)(half ? b1 : b0) * CAP;

    #pragma unroll
    for (int i = 0; i < 8; i++) acc[i] = 0.f;

    for (int k = 0; k < nmax; k += 4) {
        int2 e[4];
        #pragma unroll
        for (int j = 0; j < 4; j++) {
            int kk = k + j;
            int idx = (kk < nmy) ? kk : 0;      // pad to slot 0 (always valid)
            e[j] = __ldg(myBkt + idx);
        }
        uint4 x[4];
        float v[4];
        #pragma unroll
        for (int j = 0; j < 4; j++) {
            v[j] = (k + j < nmy) ? __int_as_float(e[j].y) : 0.f;
            x[j] = __ldg(tbl + (size_t)e[j].x * 16 + hlane);
        }
        #pragma unroll
        for (int j = 0; j < 4; j++) {
            float2 f0 = __half22float2(*reinterpret_cast<__half2*>(&x[j].x));
            float2 f1 = __half22float2(*reinterpret_cast<__half2*>(&x[j].y));
            float2 f2 = __half22float2(*reinterpret_cast<__half2*>(&x[j].z));
            float2 f3 = __half22float2(*reinterpret_cast<__half2*>(&x[j].w));
            acc[0] = fmaf(v[j], f0.x, acc[0]);
            acc[1] = fmaf(v[j], f0.y, acc[1]);
            acc[2] = fmaf(v[j], f1.x, acc[2]);
            acc[3] = fmaf(v[j], f1.y, acc[3]);
            acc[4] = fmaf(v[j], f2.x, acc[4]);
            acc[5] = fmaf(v[j], f2.y, acc[5]);
            acc[6] = fmaf(v[j], f3.x, acc[6]);
            acc[7] = fmaf(v[j], f3.y, acc[7]);
        }
    }

    #pragma unroll
    for (int i = 0; i < 8; i++) acc[i] = fmaxf(acc[i], 0.f);
    #pragma unroll
    for (int i = 0; i < 8; i++) acc[i] += __shfl_xor_sync(0xffffffffu, acc[i], 16);
}

// ---------------------------------------------------------------------------
// Gather: one warp per TASK. m-tasks (both graphs, 2x work) are scheduled
// FIRST (LPT) to avoid a straggler tail; d/p tasks follow. All plain stores.
//   task t < 20000             : m-row t (g1 pair + g2 pair, blend)
//   20000 <= t < 70000         : d-row t-20000 (graph1)
//   70000 <= t < 110000        : p-row t-70000 (graph2)
// ---------------------------------------------------------------------------
#define NTASKS 110000

__global__ void __launch_bounds__(256) gather_kernel(const float* __restrict__ inter,
                                                     float4* __restrict__ out) {
    int task = (blockIdx.x * blockDim.x + threadIdx.x) >> 5;
    int lane = threadIdx.x & 31;
    if (task >= NTASKS) return;
    int half  = lane >> 4;
    int hlane = lane & 15;

    float res8[8];
    int outRow;
    float f = 2.f;

    if (task < MEDNUM) {                        // m-row: both graphs
        int m = task;
        float a1[8], a2[8];
        pair_core(g_bkt1, DIAGNUM + m, N1 + DIAGNUM + m, 0,
                  reinterpret_cast<const uint4*>(g_e1), half, hlane, a1);
        pair_core(g_bkt2, PRONUM + m, N2 + PRONUM + m, 2 * N1,
                  reinterpret_cast<const uint4*>(g_e2), half, hlane, a2);
        float t = __ldg(inter);
        float u = 1.f - t;
        #pragma unroll
        for (int i = 0; i < 8; i++) res8[i] = t * a1[i] + u * a2[i];
        outRow = m;
    } else if (task < MEDNUM + DIAGNUM) {       // d-row, graph1
        int r = task - MEDNUM;
        pair_core(g_bkt1, r, N1 + r, 0,
                  reinterpret_cast<const uint4*>(g_e1), half, hlane, res8);
        outRow = MEDNUM + r;
    } else {                                    // p-row, graph2
        int r = task - MEDNUM - DIAGNUM;
        pair_core(g_bkt2, r, N2 + r, 2 * N1,
                  reinterpret_cast<const uint4*>(g_e2), half, hlane, res8);
        outRow = MEDNUM + DIAGNUM + r;
    }

    float4 res = half ? make_float4(res8[4], res8[5], res8[6], res8[7])
                      : make_float4(res8[0], res8[1], res8[2], res8[3]);
    res.x *= f; res.y *= f; res.z *= f; res.w *= f;
    out[(size_t)outRow * 32 + 2 * hlane + half] = res;
}

// ---------------------------------------------------------------------------
extern "C" void kernel_launch(void* const* d_in, const int* in_sizes, int n_in,
                              void* d_out, int out_size) {
    const int*   a1r = (const int*)d_in[0];
    const int*   a1c = (const int*)d_in[1];
    const float* a1v = (const float*)d_in[2];
    const int*   a2r = (const int*)d_in[3];
    const int*   a2c = (const int*)d_in[4];
    const float* a2v = (const float*)d_in[5];
    const float4* dE = (const float4*)d_in[6];
    const float4* mE = (const float4*)d_in[7];
    const float4* pE = (const float4*)d_in[8];
    const float* inter = (const float*)d_in[9];
    float4* out = (float4*)d_out;

    int2* bkt1;  cudaGetSymbolAddress((void**)&bkt1, g_bkt1);
    int2* bkt2;  cudaGetSymbolAddress((void**)&bkt2, g_bkt2);

    // 1. Zero counters (tiny)
    {
        int threads = 256;
        int blocks = (NCNT + threads - 1) / threads;
        zero_cnt_kernel<<<blocks, threads>>>();
    }

    // 2. Fused bucket (first, longer) + fp16 conversion (fills remaining SMs)
    {
        prep_kernel<<<BUCKET_BLOCKS + CONV_BLOCKS, BUCKET_THREADS>>>(
            a1r, a1c, a1v, a2r, a2c, a2v, bkt1, bkt2, dE, mE, pE);
    }

    // 3. Gather: m-tasks first (2x work), then d/p; all plain stores
    {
        int threads = 256;
        int blocks = (NTASKS * 32 + threads - 1) / threads;
        gather_kernel<<<blocks, threads>>>(inter, out);
    }
}